// round 16
// baseline (speedup 1.0000x reference)
#include <cuda_runtime.h>

// ============================================================================
// STGCNEncoder — v9: 3-kernel split for per-phase ncu attribution.
// Only row 0 of the GCN output feeds the GRU.
//  kA: stream dst, min-trick collects srcs of dst==0 edges. No barriers.
//  kB: per-block u8 presence table (smem) over srcs (first-wins slots),
//      stream dst/lo-words counting set membership. No barriers.
//  kC: encoder GEMVs + gh, one grid barrier, block-0 tail (xsum,g0,gi,gates).
// G=296, B=1024 (2 CTAs/SM). Kernel boundaries replace grid barriers 1+2.
// ============================================================================

#define G    296
#define B    1024
#define STR  (G * B)
#define CAP  2048

__device__ unsigned long long g_bar;
__device__ int   g_cnt;                    // reset by kC tail
__device__ int   g_srcs[CAP];
__device__ int   g_nodecnt[CAP + 2];       // reset by kC tail
__device__ float g_ybuf[CAP + 1][128];
__device__ float g_gh[768];

extern __shared__ char sMem[];             // kB: u8 presence table (NPAD bytes)

__device__ __forceinline__ void gbar() {
    __threadfence();
    __syncthreads();
    if (threadIdx.x == 0) {
        unsigned long long t = atomicAdd(&g_bar, 1ULL);
        unsigned long long target = t - (t % G) + G;
        volatile unsigned long long* p = &g_bar;
        while (*p < target) {}
    }
    __syncthreads();
    __threadfence();
}

__device__ __forceinline__ void hitcnt(int sval) {
    int p = atomicAdd(&g_cnt, 1);
    if (p < CAP) g_srcs[p] = sval;
}

__device__ __forceinline__ bool detect64(const unsigned* __restrict__ w, int E,
                                         int* sBad) {
    if (threadIdx.x == 0) *sBad = 0;
    __syncthreads();
    int bad = 0;
    for (int i = threadIdx.x; i < 2048 && i < E; i += B) bad |= (int)w[2 * i + 1];
    if (bad) atomicOr(sBad, 1);
    __syncthreads();
    return (*sBad == 0);
}

// ---------------------------- kA: collect --------------------------------
__global__ void __launch_bounds__(B, 2) k_passA(const unsigned* __restrict__ w, int E) {
    __shared__ int sBad;
    const int gid = blockIdx.x * B + threadIdx.x;
    const bool is64 = detect64(w, E, &sBad);

    if (is64) {
        const long long* srcq = (const long long*)w;
        if ((E & 1) == 0) {
            const uint4* dv = (const uint4*)(w + 2L * E);   // {lo,hi,lo,hi}
            int nv = E >> 1;
            int i = gid;
            for (; i + STR < nv; i += 2 * STR) {
                uint4 v0 = dv[i], v1 = dv[i + STR];
                if (min(min(v0.x, v0.z), min(v1.x, v1.z)) == 0) {
                    long e0 = 2L * i, e1 = 2L * (i + STR);
                    if (v0.x == 0) hitcnt((int)srcq[e0]);
                    if (v0.z == 0) hitcnt((int)srcq[e0 + 1]);
                    if (v1.x == 0) hitcnt((int)srcq[e1]);
                    if (v1.z == 0) hitcnt((int)srcq[e1 + 1]);
                }
            }
            for (; i < nv; i += STR) {
                uint4 v = dv[i];
                if (min(v.x, v.z) == 0) {
                    long e = 2L * i;
                    if (v.x == 0) hitcnt((int)srcq[e]);
                    if (v.z == 0) hitcnt((int)srcq[e + 1]);
                }
            }
        } else {
            const long long* dst = srcq + E;
            for (long i = gid; i < E; i += STR)
                if (dst[i] == 0) hitcnt((int)srcq[i]);
        }
    } else {
        const int* srci = (const int*)w;
        if ((E & 3) == 0) {
            const uint4* dv = (const uint4*)(w + E);
            int nv = E >> 2;
            int i = gid;
            for (; i + STR < nv; i += 2 * STR) {
                uint4 v0 = dv[i], v1 = dv[i + STR];
                unsigned m = min(min(min(v0.x, v0.y), min(v0.z, v0.w)),
                                 min(min(v1.x, v1.y), min(v1.z, v1.w)));
                if (m == 0) {
                    long e0 = 4L * i, e1 = 4L * (i + STR);
                    if (v0.x == 0) hitcnt(srci[e0]);
                    if (v0.y == 0) hitcnt(srci[e0 + 1]);
                    if (v0.z == 0) hitcnt(srci[e0 + 2]);
                    if (v0.w == 0) hitcnt(srci[e0 + 3]);
                    if (v1.x == 0) hitcnt(srci[e1]);
                    if (v1.y == 0) hitcnt(srci[e1 + 1]);
                    if (v1.z == 0) hitcnt(srci[e1 + 2]);
                    if (v1.w == 0) hitcnt(srci[e1 + 3]);
                }
            }
            for (; i < nv; i += STR) {
                uint4 v = dv[i];
                if (min(min(v.x, v.y), min(v.z, v.w)) == 0) {
                    long e = 4L * i;
                    if (v.x == 0) hitcnt(srci[e]);
                    if (v.y == 0) hitcnt(srci[e + 1]);
                    if (v.z == 0) hitcnt(srci[e + 2]);
                    if (v.w == 0) hitcnt(srci[e + 3]);
                }
            }
        } else {
            const int* dst = srci + E;
            for (long i = gid; i < E; i += STR)
                if (dst[i] == 0) hitcnt(srci[i]);
        }
    }
}

// ---------------------------- kB: count ----------------------------------
__global__ void __launch_bounds__(B, 2) k_passB(const unsigned* __restrict__ w,
                                                int E, int N) {
    __shared__ int sBad;
    __shared__ int sS[CAP];
    const int t = threadIdx.x;
    const int gid = blockIdx.x * B + t;
    const int NPAD = (N + 15) & ~15;
    unsigned char* sT8 = (unsigned char*)sMem;

    const bool is64 = detect64(w, E, &sBad);
    int cnt = g_cnt; if (cnt > CAP) cnt = CAP;

    for (int i = t; i < cnt; i += B) sS[i] = g_srcs[i];
    __syncthreads();

    const bool fast = (cnt <= 253) && (is64 ? ((E & 1) == 0) : ((E & 3) == 0));

    if (fast) {
        {   // zero u8 table
            uint4* p4 = (uint4*)sMem;
            uint4 z = make_uint4(0, 0, 0, 0);
            for (int i = t; i < (NPAD >> 4); i += B) p4[i] = z;
        }
        __syncthreads();
        if (t == 0) {   // first-wins build (descending, so i=0 wins duplicates)
            for (int i = cnt - 1; i >= 0; i--) sT8[sS[i]] = (unsigned char)(i + 1);
            if (sT8[0] == 0) sT8[0] = (unsigned char)(cnt + 1);
        }
        __syncthreads();

        if (is64) {
            const uint4* dv = (const uint4*)(w + 2L * E);
            int nv = E >> 1;
            int i = gid;
            for (; i + STR < nv; i += 2 * STR) {
                uint4 v0 = dv[i], v1 = dv[i + STR];
                unsigned p0 = sT8[v0.x], p1 = sT8[v0.z];
                unsigned p2 = sT8[v1.x], p3 = sT8[v1.z];
                if ((p0 | p1) | (p2 | p3)) {
                    if (p0) atomicAdd(&g_nodecnt[p0 - 1], 1);
                    if (p1) atomicAdd(&g_nodecnt[p1 - 1], 1);
                    if (p2) atomicAdd(&g_nodecnt[p2 - 1], 1);
                    if (p3) atomicAdd(&g_nodecnt[p3 - 1], 1);
                }
            }
            for (; i < nv; i += STR) {
                uint4 v = dv[i];
                unsigned p0 = sT8[v.x], p1 = sT8[v.z];
                if (p0) atomicAdd(&g_nodecnt[p0 - 1], 1);
                if (p1) atomicAdd(&g_nodecnt[p1 - 1], 1);
            }
        } else {
            const uint4* dv = (const uint4*)(w + E);
            int nv = E >> 2;
            int i = gid;
            for (; i + STR < nv; i += 2 * STR) {
                uint4 v0 = dv[i], v1 = dv[i + STR];
                unsigned p0 = sT8[v0.x], p1 = sT8[v0.y], p2 = sT8[v0.z], p3 = sT8[v0.w];
                unsigned q0 = sT8[v1.x], q1 = sT8[v1.y], q2 = sT8[v1.z], q3 = sT8[v1.w];
                if (((p0 | p1) | (p2 | p3)) | ((q0 | q1) | (q2 | q3))) {
                    if (p0) atomicAdd(&g_nodecnt[p0 - 1], 1);
                    if (p1) atomicAdd(&g_nodecnt[p1 - 1], 1);
                    if (p2) atomicAdd(&g_nodecnt[p2 - 1], 1);
                    if (p3) atomicAdd(&g_nodecnt[p3 - 1], 1);
                    if (q0) atomicAdd(&g_nodecnt[q0 - 1], 1);
                    if (q1) atomicAdd(&g_nodecnt[q1 - 1], 1);
                    if (q2) atomicAdd(&g_nodecnt[q2 - 1], 1);
                    if (q3) atomicAdd(&g_nodecnt[q3 - 1], 1);
                }
            }
            for (; i < nv; i += STR) {
                uint4 v = dv[i];
                unsigned p0 = sT8[v.x], p1 = sT8[v.y], p2 = sT8[v.z], p3 = sT8[v.w];
                if (p0) atomicAdd(&g_nodecnt[p0 - 1], 1);
                if (p1) atomicAdd(&g_nodecnt[p1 - 1], 1);
                if (p2) atomicAdd(&g_nodecnt[p2 - 1], 1);
                if (p3) atomicAdd(&g_nodecnt[p3 - 1], 1);
            }
        }
    } else {
        // slow-but-correct fallback: first-match linear scan (cnt>253: ~never)
        auto scan1 = [&](int d) {
            int sl = -1;
            for (int j = 0; j < cnt; j++) if (sS[j] == d) { sl = j; break; }
            if (sl < 0 && d == 0) sl = cnt;
            if (sl >= 0) atomicAdd(&g_nodecnt[sl], 1);
        };
        if (is64) {
            const long long* dst = ((const long long*)w) + E;
            for (long i = gid; i < E; i += STR) scan1((int)dst[i]);
        } else {
            const int* dst = ((const int*)w) + E;
            for (long i = gid; i < E; i += STR) scan1((int)dst[i]);
        }
    }
}

// ---------------------------- kC: rest -----------------------------------
__global__ void __launch_bounds__(B, 2) k_rest(
    const float* __restrict__ nf, const float* __restrict__ h,
    const float* __restrict__ W_enc, const float* __restrict__ b_enc,
    const float* __restrict__ W_gcn, const float* __restrict__ b_gcn,
    const float* __restrict__ W_ih, const float* __restrict__ W_hh,
    const float* __restrict__ b_ih, const float* __restrict__ b_hh,
    float* __restrict__ out)
{
    __shared__ int   sS[CAP];
    __shared__ float sF[64];
    __shared__ float sTail[2048];          // sX|sG0|sGi|sPar

    const int t = threadIdx.x, lane = t & 31, wid = t >> 5;
    const int bid = blockIdx.x;

    int cnt = g_cnt; if (cnt > CAP) cnt = CAP;
    const int M = cnt + 1;

    for (int i = t; i < cnt; i += B) sS[i] = g_srcs[i];
    __syncthreads();

    // first-wins slot lookup (matches kB table semantics)
    auto slot_of = [&](int s) {
        for (int j = 0; j < cnt; j++) if (sS[j] == s) return j;
        return cnt;                         // only node 0 lands here
    };

    if (bid < M) {
        const float rd0 = rsqrtf((float)g_nodecnt[slot_of(0)] + 1.0f);
        for (int i = bid; i < M; i += G) {
            int s = (i < cnt) ? sS[i] : 0;
            float wt = rsqrtf((float)g_nodecnt[slot_of(s)] + 1.0f) * rd0;
            if (t < 64) sF[t] = nf[(long)s * 64 + t];
            __syncthreads();
            float f0 = sF[lane], f1 = sF[lane + 32];
            #pragma unroll
            for (int jj = 0; jj < 4; jj++) {
                int j = wid * 4 + jj;
                const float* wr = W_enc + j * 64;
                float a = wr[lane] * f0 + wr[lane + 32] * f1;
                #pragma unroll
                for (int o = 16; o; o >>= 1) a += __shfl_down_sync(0xffffffffu, a, o);
                if (lane == 0) g_ybuf[i][j] = wt * fmaxf(a + b_enc[j], 0.0f);
            }
            __syncthreads();
        }
    }
    if (bid >= 272) {
        int r = (bid - 272) * 32 + wid;
        if (r < 768) {
            const float* wr = W_hh + r * 256;
            float a = 0.0f;
            #pragma unroll
            for (int kk = 0; kk < 8; kk++) a += wr[kk * 32 + lane] * h[kk * 32 + lane];
            #pragma unroll
            for (int o = 16; o; o >>= 1) a += __shfl_down_sync(0xffffffffu, a, o);
            if (lane == 0) g_gh[r] = a + b_hh[r];
        }
    }
    gbar();

    if (bid == 0) {
        float* sX   = sTail;
        float* sG0  = sTail + 128;
        float* sGi  = sTail + 256;
        float* sPar = sTail + 1024;
        {
            int grp = t >> 7, col = t & 127;
            float xs = 0.0f;
            for (int i = grp; i < M; i += 8) xs += g_ybuf[i][col];
            sPar[grp * 128 + col] = xs;
        }
        __syncthreads();
        if (t < 128) {
            float s = 0.0f;
            #pragma unroll
            for (int g2 = 0; g2 < 8; g2++) s += sPar[g2 * 128 + t];
            sX[t] = s;
        }
        __syncthreads();
        #pragma unroll
        for (int jj = 0; jj < 4; jj++) {
            int j = wid * 4 + jj;
            float a = 0.0f;
            #pragma unroll
            for (int kk = 0; kk < 4; kk++)
                a += W_gcn[j * 128 + kk * 32 + lane] * sX[kk * 32 + lane];
            #pragma unroll
            for (int o = 16; o; o >>= 1) a += __shfl_down_sync(0xffffffffu, a, o);
            if (lane == 0) sG0[j] = fmaxf(a + b_gcn[j], 0.0f);
        }
        __syncthreads();
        #pragma unroll
        for (int q = 0; q < 24; q++) {
            int r = q * 32 + wid;
            const float* wr = W_ih + r * 128;
            float a = 0.0f;
            #pragma unroll
            for (int kk = 0; kk < 4; kk++)
                a += wr[kk * 32 + lane] * sG0[kk * 32 + lane];
            #pragma unroll
            for (int o = 16; o; o >>= 1) a += __shfl_down_sync(0xffffffffu, a, o);
            if (lane == 0) sGi[r] = a + b_ih[r];
        }
        __syncthreads();
        if (t < 256) {
            float r_ = 1.0f / (1.0f + expf(-(sGi[t] + g_gh[t])));
            float z  = 1.0f / (1.0f + expf(-(sGi[256 + t] + g_gh[256 + t])));
            float nn = tanhf(sGi[512 + t] + r_ * g_gh[512 + t]);
            out[t] = (1.0f - z) * nn + z * h[t];
        }
        for (int i = t; i < cnt + 2; i += B) g_nodecnt[i] = 0;
        if (t == 0) g_cnt = 0;
    }
}

// ---------------------------------------------------------------------------
extern "C" void kernel_launch(void* const* d_in, const int* in_sizes, int n_in,
                              void* d_out, int out_size) {
    const float* nf    = (const float*)d_in[0];
    // d_in[1] = edge_attr (unused by reference)
    const float* h     = (const float*)d_in[2];
    const float* W_enc = (const float*)d_in[3];
    const float* b_enc = (const float*)d_in[4];
    const float* W_gcn = (const float*)d_in[5];
    const float* b_gcn = (const float*)d_in[6];
    const float* W_ih  = (const float*)d_in[7];
    const float* W_hh  = (const float*)d_in[8];
    const float* b_ih  = (const float*)d_in[9];
    const float* b_hh  = (const float*)d_in[10];
    const unsigned* ei = (const unsigned*)d_in[11];
    int E = in_sizes[11] / 2;
    int N = in_sizes[0] / 64;
    float* out = (float*)d_out;

    int npad = (N + 15) & ~15;
    cudaFuncSetAttribute(k_passB, cudaFuncAttributeMaxDynamicSharedMemorySize, npad);

    k_passA<<<G, B>>>(ei, E);
    k_passB<<<G, B, npad>>>(ei, E, N);
    k_rest <<<G, B>>>(nf, h, W_enc, b_enc, W_gcn, b_gcn,
                      W_ih, W_hh, b_ih, b_hh, out);
}

// round 17
// speedup vs baseline: 1.1115x; 1.1115x over previous
#include <cuda_runtime.h>

// ============================================================================
// STGCNEncoder — v10: register-resident second pass.
// Only row 0 of the GCN output feeds the GRU.
//  Phase 1: ONE stream over dst (12 uint4/thread); lo-words stay in registers;
//           min-trick collects srcs of dst==0 edges.
//  Phase 2: u8 presence table in smem (serial first-wins build, identical in
//           every block) tested against the REGISTER-resident values: the
//           second 25.6MB global read is gone (~9us -> <1us).
//  Phase 3: encoder GEMVs (block/term) + gh overlap.  Phase 4: block-0 tail.
//  G=148, B=1024, 1 CTA/SM (64-reg budget holds 24 data regs + machinery).
// ============================================================================

#define G    148
#define B    1024
#define STR  (G * B)
#define CAP  2048
#define K64  12            // uint4 loads/thread (int64): 24 edges capacity
#define K32  6             // uint4 loads/thread (int32): 24 edges capacity

__device__ unsigned long long g_bar;
__device__ int   g_cnt;
__device__ int   g_srcs[CAP];
__device__ int   g_nodecnt[CAP + 2];
__device__ float g_ybuf[CAP + 1][128];
__device__ float g_gh[768];

extern __shared__ char sMem[];       // u8 presence table (NPAD); tail reuse

__device__ __forceinline__ void gbar() {
    __threadfence();
    __syncthreads();
    if (threadIdx.x == 0) {
        unsigned long long t = atomicAdd(&g_bar, 1ULL);
        unsigned long long target = t - (t % G) + G;
        volatile unsigned long long* p = &g_bar;
        while (*p < target) {}
    }
    __syncthreads();
    __threadfence();
}

__device__ __forceinline__ void hitcnt(int sval) {
    int p = atomicAdd(&g_cnt, 1);
    if (p < CAP) g_srcs[p] = sval;
}

__global__ void __launch_bounds__(B, 1) k_fused(
    const float* __restrict__ nf, const float* __restrict__ h,
    const float* __restrict__ W_enc, const float* __restrict__ b_enc,
    const float* __restrict__ W_gcn, const float* __restrict__ b_gcn,
    const float* __restrict__ W_ih, const float* __restrict__ W_hh,
    const float* __restrict__ b_ih, const float* __restrict__ b_hh,
    const unsigned* __restrict__ w, int E, int N, float* __restrict__ out)
{
    __shared__ int   sBad;
    __shared__ int   sS[CAP];
    __shared__ float sF[64];
    __shared__ float sTail[2048];

    const int t = threadIdx.x, lane = t & 31, wid = t >> 5;
    const int bid = blockIdx.x;
    const int gid = bid * B + t;
    const int NPAD = (N + 15) & ~15;
    unsigned char* sT8 = (unsigned char*)sMem;

    // ---- init: zero u8 table + dtype detect ----
    {
        uint4* p4 = (uint4*)sMem;
        uint4 z = make_uint4(0, 0, 0, 0);
        for (int i = t; i < (NPAD >> 4); i += B) p4[i] = z;
    }
    if (t == 0) sBad = 0;
    __syncthreads();
    {
        int bad = 0;
        for (int i = t; i < 2048 && i < E; i += B) bad |= (int)w[2 * i + 1];
        if (bad) atomicOr(&sBad, 1);
    }
    __syncthreads();
    const bool is64 = (sBad == 0);
    const bool fast = is64 ? (((E & 1) == 0) && ((E >> 1) <= K64 * STR))
                           : (((E & 3) == 0) && ((E >> 2) <= K32 * STR));

    unsigned d[2 * K64];   // register-resident lo-words (24)

    // ---------------- Phase 1: the ONLY full read of dst ----------------
    if (fast) {
        if (is64) {
            const long long* srcq = (const long long*)w;
            const uint4* dv = (const uint4*)(w + 2L * E);   // {lo,hi,lo,hi}
            const int nv = E >> 1;
            #pragma unroll
            for (int j = 0; j < K64; j++) {
                int idx = gid + j * STR;
                unsigned lo0 = 1u, lo1 = 1u;                 // benign when OOB
                if (idx < nv) {
                    uint4 v = dv[idx];
                    lo0 = v.x; lo1 = v.z;
                    if (min(lo0, lo1) == 0) {
                        long e = 2L * idx;
                        if (lo0 == 0) hitcnt((int)srcq[e]);
                        if (lo1 == 0) hitcnt((int)srcq[e + 1]);
                    }
                }
                d[2 * j] = lo0; d[2 * j + 1] = lo1;
            }
        } else {
            const int* srci = (const int*)w;
            const uint4* dv = (const uint4*)(w + E);
            const int nv = E >> 2;
            #pragma unroll
            for (int j = 0; j < K32; j++) {
                int idx = gid + j * STR;
                unsigned a0 = 1u, a1 = 1u, a2 = 1u, a3 = 1u;
                if (idx < nv) {
                    uint4 v = dv[idx];
                    a0 = v.x; a1 = v.y; a2 = v.z; a3 = v.w;
                    if (min(min(a0, a1), min(a2, a3)) == 0) {
                        long e = 4L * idx;
                        if (a0 == 0) hitcnt(srci[e]);
                        if (a1 == 0) hitcnt(srci[e + 1]);
                        if (a2 == 0) hitcnt(srci[e + 2]);
                        if (a3 == 0) hitcnt(srci[e + 3]);
                    }
                }
                d[4 * j] = a0; d[4 * j + 1] = a1; d[4 * j + 2] = a2; d[4 * j + 3] = a3;
            }
        }
    } else {
        // fallback pass A: scalar global scan
        if (is64) {
            const long long* srcq = (const long long*)w;
            const long long* dst = srcq + E;
            for (long i = gid; i < E; i += STR)
                if (dst[i] == 0) hitcnt((int)srcq[i]);
        } else {
            const int* srci = (const int*)w;
            const int* dst = srci + E;
            for (long i = gid; i < E; i += STR)
                if (dst[i] == 0) hitcnt(srci[i]);
        }
    }
    gbar();  // -------- barrier 1 --------

    int cnt = g_cnt; if (cnt > CAP) cnt = CAP;
    const int M = cnt + 1;                       // + node-0 self-loop term
    const bool fastB = fast && (cnt <= 253);

    for (int i = t; i < cnt; i += B) sS[i] = g_srcs[i];
    __syncthreads();

    // ---------------- Phase 2: register-resident membership count --------
    if (fastB) {
        // serial first-wins build (descending: i=0 wins dups) — identical
        // table in every block, no cross-block race.
        if (t == 0) {
            for (int i = cnt - 1; i >= 0; i--) sT8[sS[i]] = (unsigned char)(i + 1);
            if (sT8[0] == 0) sT8[0] = (unsigned char)(cnt + 1);
        }
        __syncthreads();

        if (is64) {
            const int nv = E >> 1;
            #pragma unroll
            for (int j = 0; j < K64; j++) {
                if (gid + j * STR < nv) {
                    unsigned p0 = sT8[d[2 * j]], p1 = sT8[d[2 * j + 1]];
                    if (p0 | p1) {
                        if (p0) atomicAdd(&g_nodecnt[p0 - 1], 1);
                        if (p1) atomicAdd(&g_nodecnt[p1 - 1], 1);
                    }
                }
            }
        } else {
            const int nv = E >> 2;
            #pragma unroll
            for (int j = 0; j < K32; j++) {
                if (gid + j * STR < nv) {
                    unsigned p0 = sT8[d[4 * j]],     p1 = sT8[d[4 * j + 1]];
                    unsigned p2 = sT8[d[4 * j + 2]], p3 = sT8[d[4 * j + 3]];
                    if ((p0 | p1) | (p2 | p3)) {
                        if (p0) atomicAdd(&g_nodecnt[p0 - 1], 1);
                        if (p1) atomicAdd(&g_nodecnt[p1 - 1], 1);
                        if (p2) atomicAdd(&g_nodecnt[p2 - 1], 1);
                        if (p3) atomicAdd(&g_nodecnt[p3 - 1], 1);
                    }
                }
            }
        }
    } else {
        // fallback pass B: scalar global rescan, first-match linear search
        for (long i = gid; i < E; i += STR) {
            int dd = is64 ? (int)(((const long long*)w) + E)[i]
                          : (int)(((const int*)w) + E)[i];
            int sl = -1;
            for (int j = 0; j < cnt; j++) if (sS[j] == dd) { sl = j; break; }
            if (sl < 0 && dd == 0) sl = cnt;
            if (sl >= 0) atomicAdd(&g_nodecnt[sl], 1);
        }
    }
    gbar();  // -------- barrier 2 --------

    // slot lookup consistent with first-wins table
    auto slot_of = [&](int s) {
        for (int j = 0; j < cnt; j++) if (sS[j] == s) return j;
        return cnt;                              // only node 0 lands here
    };

    // ---------------- Phase 3: encoder terms + gh overlap ----------------
    if (bid < M) {
        const float rd0 = rsqrtf((float)g_nodecnt[slot_of(0)] + 1.0f);
        for (int i = bid; i < M; i += G) {
            int s = (i < cnt) ? sS[i] : 0;
            float wt = rsqrtf((float)g_nodecnt[slot_of(s)] + 1.0f) * rd0;
            if (t < 64) sF[t] = nf[(long)s * 64 + t];
            __syncthreads();
            float f0 = sF[lane], f1 = sF[lane + 32];
            #pragma unroll
            for (int jj = 0; jj < 4; jj++) {
                int j = wid * 4 + jj;
                const float* wr = W_enc + j * 64;
                float a = wr[lane] * f0 + wr[lane + 32] * f1;
                #pragma unroll
                for (int o = 16; o; o >>= 1) a += __shfl_down_sync(0xffffffffu, a, o);
                if (lane == 0) g_ybuf[i][j] = wt * fmaxf(a + b_enc[j], 0.0f);
            }
            __syncthreads();
        }
    }
    if (bid >= 124) {                    // 24 blocks x 32 warps = 768 rows
        int r = (bid - 124) * 32 + wid;
        if (r < 768) {
            const float* wr = W_hh + r * 256;
            float a = 0.0f;
            #pragma unroll
            for (int kk = 0; kk < 8; kk++) a += wr[kk * 32 + lane] * h[kk * 32 + lane];
            #pragma unroll
            for (int o = 16; o; o >>= 1) a += __shfl_down_sync(0xffffffffu, a, o);
            if (lane == 0) g_gh[r] = a + b_hh[r];
        }
    }
    gbar();  // -------- barrier 3 --------

    // ---------------- Phase 4: block-0 tail -------------------------------
    if (bid == 0) {
        float* sX   = sTail;
        float* sG0  = sTail + 128;
        float* sGi  = sTail + 256;
        float* sPar = sTail + 1024;
        {
            int grp = t >> 7, col = t & 127;
            float xs = 0.0f;
            for (int i = grp; i < M; i += 8) xs += g_ybuf[i][col];
            sPar[grp * 128 + col] = xs;
        }
        __syncthreads();
        if (t < 128) {
            float s = 0.0f;
            #pragma unroll
            for (int g2 = 0; g2 < 8; g2++) s += sPar[g2 * 128 + t];
            sX[t] = s;
        }
        __syncthreads();
        #pragma unroll
        for (int jj = 0; jj < 4; jj++) {
            int j = wid * 4 + jj;
            float a = 0.0f;
            #pragma unroll
            for (int kk = 0; kk < 4; kk++)
                a += W_gcn[j * 128 + kk * 32 + lane] * sX[kk * 32 + lane];
            #pragma unroll
            for (int o = 16; o; o >>= 1) a += __shfl_down_sync(0xffffffffu, a, o);
            if (lane == 0) sG0[j] = fmaxf(a + b_gcn[j], 0.0f);
        }
        __syncthreads();
        #pragma unroll
        for (int q = 0; q < 24; q++) {
            int r = q * 32 + wid;
            const float* wr = W_ih + r * 128;
            float a = 0.0f;
            #pragma unroll
            for (int kk = 0; kk < 4; kk++)
                a += wr[kk * 32 + lane] * sG0[kk * 32 + lane];
            #pragma unroll
            for (int o = 16; o; o >>= 1) a += __shfl_down_sync(0xffffffffu, a, o);
            if (lane == 0) sGi[r] = a + b_ih[r];
        }
        __syncthreads();
        if (t < 256) {
            float r_ = 1.0f / (1.0f + expf(-(sGi[t] + g_gh[t])));
            float z  = 1.0f / (1.0f + expf(-(sGi[256 + t] + g_gh[256 + t])));
            float nn = tanhf(sGi[512 + t] + r_ * g_gh[512 + t]);
            out[t] = (1.0f - z) * nn + z * h[t];
        }
        for (int i = t; i < cnt + 2; i += B) g_nodecnt[i] = 0;
        if (t == 0) g_cnt = 0;
    }
}

// ---------------------------------------------------------------------------
extern "C" void kernel_launch(void* const* d_in, const int* in_sizes, int n_in,
                              void* d_out, int out_size) {
    const float* nf    = (const float*)d_in[0];
    // d_in[1] = edge_attr (unused by reference)
    const float* h     = (const float*)d_in[2];
    const float* W_enc = (const float*)d_in[3];
    const float* b_enc = (const float*)d_in[4];
    const float* W_gcn = (const float*)d_in[5];
    const float* b_gcn = (const float*)d_in[6];
    const float* W_ih  = (const float*)d_in[7];
    const float* W_hh  = (const float*)d_in[8];
    const float* b_ih  = (const float*)d_in[9];
    const float* b_hh  = (const float*)d_in[10];
    const unsigned* ei = (const unsigned*)d_in[11];
    int E = in_sizes[11] / 2;
    int N = in_sizes[0] / 64;
    float* out = (float*)d_out;

    int npad = (N + 15) & ~15;
    int smem = npad;
    if (smem < 16384) smem = 16384;
    cudaFuncSetAttribute(k_fused, cudaFuncAttributeMaxDynamicSharedMemorySize, smem);

    k_fused<<<G, B, smem>>>(nf, h, W_enc, b_enc, W_gcn, b_gcn,
                            W_ih, W_hh, b_ih, b_hh, ei, E, N, out);
}